// round 4
// baseline (speedup 1.0000x reference)
#include <cuda_runtime.h>
#include <math.h>

#define BN      40000
#define NPG     10000
#define NB      4
#define G       128
#define UNITS   32
#define FDIM    64

// ---------------- device scratch (no allocations allowed) ----------------
__device__ float g_qkv[6u * (size_t)BN * G];     // Q1,K1,V1,Q2,K2,V2 (reused x then h)
__device__ float g_xsum[(size_t)BN * G];
__device__ float g_hsum[(size_t)BN * G];
__device__ int   g_cnt[BN];
__device__ int   g_offs[BN + 1];
__device__ int   g_cur[BN];
__device__ int   g_colx[640000];
__device__ float g_stats[2048];                  // x: sum[0:512) ss[512:1024); h: +1024
__device__ float g_mean[1024];                   // x: [0:512), h: [512:1024)
__device__ float g_inv[1024];

// ---------------- helpers ----------------
__device__ __forceinline__ float leaky(float v) { return v >= 0.f ? v : 0.2f * v; }

__device__ __forceinline__ unsigned long long pk(float a, float b) {
    unsigned long long r;
    asm("mov.b64 %0, {%1, %2};" : "=l"(r) : "f"(a), "f"(b));
    return r;
}
__device__ __forceinline__ float2 unpk(unsigned long long v) {
    float2 r;
    asm("mov.b64 {%0, %1}, %2;" : "=f"(r.x), "=f"(r.y) : "l"(v));
    return r;
}
__device__ __forceinline__ void fma2(unsigned long long& d, unsigned long long a, unsigned long long b) {
    asm("fma.rn.f32x2 %0, %1, %2, %0;" : "+l"(d) : "l"(a), "l"(b));
}
__device__ __forceinline__ float dot4(float4 a, float4 b) {
    return fmaf(a.x, b.x, fmaf(a.y, b.y, fmaf(a.z, b.z, a.w * b.w)));
}
__device__ __forceinline__ void online_update(float p, float4 v, float& m, float& s, float4& acc) {
    // warp-uniform branch (p, m identical across lanes)
    if (p <= m) {
        float w = __expf(p - m);
        s += w;
        acc.x = fmaf(w, v.x, acc.x); acc.y = fmaf(w, v.y, acc.y);
        acc.z = fmaf(w, v.z, acc.z); acc.w = fmaf(w, v.w, acc.w);
    } else {
        float sc = __expf(m - p);
        s = fmaf(s, sc, 1.f);
        acc.x = fmaf(acc.x, sc, v.x); acc.y = fmaf(acc.y, sc, v.y);
        acc.z = fmaf(acc.z, sc, v.z); acc.w = fmaf(acc.w, sc, v.w);
        m = p;
    }
}
__device__ __forceinline__ float sigm(float x) { return 1.f / (1.f + __expf(-x)); }

// ---------------- CSR build ----------------
__global__ void zero_k() {
    int i = blockIdx.x * 256 + threadIdx.x;
    if (i < BN)   g_cnt[i] = 0;
    if (i < 2048) g_stats[i] = 0.f;
}
__global__ void hist_k(const int* __restrict__ ei, int E) {
    int e = blockIdx.x * 256 + threadIdx.x;
    if (e < E) atomicAdd(&g_cnt[ei[e]], 1);
}
__global__ void scan_k(int E) {
    __shared__ int sh[1024];
    int t = threadIdx.x;
    int base = t * 40;
    int n = BN - base; n = n < 0 ? 0 : (n > 40 ? 40 : n);
    int s = 0;
    for (int i = 0; i < n; i++) s += g_cnt[base + i];
    sh[t] = s; __syncthreads();
    for (int off = 1; off < 1024; off <<= 1) {
        int v = (t >= off) ? sh[t - off] : 0;
        __syncthreads();
        sh[t] += v;
        __syncthreads();
    }
    int run = sh[t] - s;  // exclusive prefix
    for (int i = 0; i < n; i++) {
        g_offs[base + i] = run; g_cur[base + i] = run;
        run += g_cnt[base + i];
    }
    if (t == 0) g_offs[BN] = E;
}
__global__ void scat_k(const int* __restrict__ ei, int E) {
    int e = blockIdx.x * 256 + threadIdx.x;
    if (e < E) {
        int r = ei[e];
        int pos = atomicAdd(&g_cur[r], 1);
        g_colx[pos] = ei[E + e];
    }
}

// ---------------- GEMM: out[m] = (leaky)(x @ W + b), 6 matrices, f32x2 pipes ----------------
template <int DIN>
__global__ __launch_bounds__(256) void gemm_qkv(
    const float* __restrict__ x,
    const float* __restrict__ w0, const float* __restrict__ w1, const float* __restrict__ w2,
    const float* __restrict__ w3, const float* __restrict__ w4, const float* __restrict__ w5,
    const float* __restrict__ b0, const float* __restrict__ b1,
    const float* __restrict__ b3, const float* __restrict__ b4)
{
    __shared__ __align__(16) float ws[DIN * 128];
    __shared__ __align__(16) float xsT[DIN * 64];
    int tid = threadIdx.x;
    int m = blockIdx.y;
    const float* w = (m == 0) ? w0 : (m == 1) ? w1 : (m == 2) ? w2 : (m == 3) ? w3 : (m == 4) ? w4 : w5;
    const float* bias = (m == 0) ? b0 : (m == 1) ? b1 : (m == 3) ? b3 : (m == 4) ? b4 : (const float*)0;
    bool act = (m % 3) != 2;
    bool isQ = (m % 3) == 0;     // Q matrices are streamed-once by gat_agg -> evict-first
    int row0 = blockIdx.x * 64;

    const float4* w4p = (const float4*)w;
    float4* ws4 = (float4*)ws;
    #pragma unroll
    for (int i = tid; i < DIN * 32; i += 256) ws4[i] = w4p[i];

    for (int i4 = tid; i4 < DIN * 16; i4 += 256) {
        int r = (i4 * 4) / DIN, k0 = (i4 * 4) % DIN;
        float4 v = *(const float4*)(x + (size_t)(row0 + r) * DIN + k0);
        float vv[4] = {v.x, v.y, v.z, v.w};
        #pragma unroll
        for (int j = 0; j < 4; j++) {
            int k = k0 + j;
            xsT[k * 64 + ((((r >> 2) ^ (k & 15)) << 2) | (r & 3))] = vv[j];
        }
    }
    __syncthreads();

    int lane = tid & 31, warp = tid >> 5;
    int r0 = warp * 8;
    unsigned long long acc[8][2];
    #pragma unroll
    for (int r = 0; r < 8; r++) { acc[r][0] = 0ull; acc[r][1] = 0ull; }

    #pragma unroll 8
    for (int k = 0; k < DIN; k++) {
        float4 wv = *(const float4*)&ws[k * 128 + lane * 4];
        unsigned long long w01 = pk(wv.x, wv.y), w23 = pk(wv.z, wv.w);
        int sw = k & 15;
        float4 a0 = *(const float4*)&xsT[k * 64 + (((r0 >> 2) ^ sw) << 2)];
        float4 a1 = *(const float4*)&xsT[k * 64 + ((((r0 >> 2) + 1) ^ sw) << 2)];
        float ar[8] = {a0.x, a0.y, a0.z, a0.w, a1.x, a1.y, a1.z, a1.w};
        #pragma unroll
        for (int r = 0; r < 8; r++) {
            unsigned long long aa = pk(ar[r], ar[r]);
            fma2(acc[r][0], aa, w01);
            fma2(acc[r][1], aa, w23);
        }
    }

    float4 bv = make_float4(0.f, 0.f, 0.f, 0.f);
    if (bias) bv = ((const float4*)bias)[lane];
    float* out = g_qkv + (size_t)m * (size_t)BN * G;
    #pragma unroll
    for (int r = 0; r < 8; r++) {
        float2 lo = unpk(acc[r][0]), hi = unpk(acc[r][1]);
        float4 res = make_float4(lo.x + bv.x, lo.y + bv.y, hi.x + bv.z, hi.y + bv.w);
        if (act) { res.x = leaky(res.x); res.y = leaky(res.y); res.z = leaky(res.z); res.w = leaky(res.w); }
        float4* dst = (float4*)(out + (size_t)(row0 + r0 + r) * 128 + lane * 4);
        if (isQ) __stcs(dst, res); else *dst = res;
    }
}

// ---------------- fused dual-GAT aggregation ----------------
// warp per node; warp split into 4 groups of 8 lanes; each group scores one edge
// (3-shfl reduce instead of 5), 4 edges in flight; V accumulation stays full-warp.
__global__ __launch_bounds__(256) void gat_agg(
    const float* __restrict__ bv1, const float* __restrict__ bv2, int which)
{
    int wid = (blockIdx.x * 256 + threadIdx.x) >> 5;
    if (wid >= BN) return;
    int lane = threadIdx.x & 31;
    int sub = lane & 7;          // position within 8-lane group
    int grp = lane >> 3;         // group id 0..3

    const float4* B4 = (const float4*)g_qkv;
    const size_t M4 = (size_t)BN * 32;
    const float4* Q1 = B4;
    const float4* K1 = B4 + M4;
    const float4* V1 = B4 + M4 * 2;
    const float4* Q2 = B4 + M4 * 3;
    const float4* K2 = B4 + M4 * 4;
    const float4* V2 = B4 + M4 * 5;

    size_t selfrow = (size_t)wid * 32;

    // Q in group layout: lane holds cols [sub*16, sub*16+16) (4 float4), streamed-once
    float4 q1s[4], q2s[4];
    #pragma unroll
    for (int t = 0; t < 4; t++) {
        q1s[t] = __ldcs(Q1 + selfrow + sub * 4 + t);
        q2s[t] = __ldcs(Q2 + selfrow + sub * 4 + t);
    }

    // self-loop score (all 4 groups compute the same value)
    float p1 = 0.f, p2 = 0.f;
    #pragma unroll
    for (int t = 0; t < 4; t++) {
        p1 += dot4(q1s[t], K1[selfrow + sub * 4 + t]);
        p2 += dot4(q2s[t], K2[selfrow + sub * 4 + t]);
    }
    #pragma unroll
    for (int off = 1; off < 8; off <<= 1) {
        p1 += __shfl_xor_sync(0xffffffffu, p1, off);
        p2 += __shfl_xor_sync(0xffffffffu, p2, off);
    }
    float m1 = p1, s1 = 1.f, m2 = p2, s2 = 1.f;
    float4 acc1 = V1[selfrow + lane];   // acc layout: cols [lane*4, lane*4+4)
    float4 acc2 = V2[selfrow + lane];

    int start = g_offs[wid], end = g_offs[wid + 1];
    for (int base = start; base < end; base += 32) {
        int e = base + lane;
        int cv = (e < end) ? __ldcs(&g_colx[e]) : 0;
        int cnt = min(32, end - base);
        for (int j = 0; j < cnt; j += 4) {
            int nj = cnt - j; if (nj > 4) nj = 4;
            // group grp scores edge j+grp (garbage for grp>=nj, unused)
            int srcg = __shfl_sync(0xffffffffu, cv, j + grp);
            size_t kb = (size_t)srcg * 32 + sub * 4;
            float pa = 0.f, pb = 0.f;
            #pragma unroll
            for (int t = 0; t < 4; t++) {
                pa += dot4(q1s[t], K1[kb + t]);
                pb += dot4(q2s[t], K2[kb + t]);
            }
            #pragma unroll
            for (int off = 1; off < 8; off <<= 1) {
                pa += __shfl_xor_sync(0xffffffffu, pa, off);
                pb += __shfl_xor_sync(0xffffffffu, pb, off);
            }
            float sa[4], sb[4]; int srcs[4];
            #pragma unroll
            for (int jj = 0; jj < 4; jj++) {
                sa[jj] = __shfl_sync(0xffffffffu, pa, jj * 8);
                sb[jj] = __shfl_sync(0xffffffffu, pb, jj * 8);
                srcs[jj] = __shfl_sync(0xffffffffu, cv, j + jj);
            }
            if (nj == 4) {
                // hoist all V loads for MLP, then 8 sequential uniform updates
                float4 v1[4], v2[4];
                #pragma unroll
                for (int jj = 0; jj < 4; jj++) {
                    size_t vi = (size_t)srcs[jj] * 32 + lane;
                    v1[jj] = V1[vi]; v2[jj] = V2[vi];
                }
                #pragma unroll
                for (int jj = 0; jj < 4; jj++) {
                    online_update(sa[jj], v1[jj], m1, s1, acc1);
                    online_update(sb[jj], v2[jj], m2, s2, acc2);
                }
            } else {
                for (int jj = 0; jj < nj; jj++) {
                    size_t vi = (size_t)srcs[jj] * 32 + lane;
                    float4 v1 = V1[vi], v2 = V2[vi];
                    online_update(sa[jj], v1, m1, s1, acc1);
                    online_update(sb[jj], v2, m2, s2, acc2);
                }
            }
        }
    }

    float r1 = 1.f / s1, r2 = 1.f / s2;
    float4 bb1 = ((const float4*)bv1)[lane];
    float4 bb2 = ((const float4*)bv2)[lane];
    float4 o;
    o.x = acc1.x * r1 + bb1.x + acc2.x * r2 + bb2.x;
    o.y = acc1.y * r1 + bb1.y + acc2.y * r2 + bb2.y;
    o.z = acc1.z * r1 + bb1.z + acc2.z * r2 + bb2.z;
    o.w = acc1.w * r1 + bb1.w + acc2.w * r2 + bb2.w;
    float* outsum = which ? g_hsum : g_xsum;
    __stcs((float4*)(outsum + (selfrow + lane) * 4), o);
}

// ---------------- graph-norm statistics ----------------
__global__ void stats_k(int which) {
    const float* buf = which ? g_hsum : g_xsum;
    int statbase = which ? 1024 : 0;
    int b = blockIdx.y, chunk = blockIdx.x, c = threadIdx.x;  // 128 threads
    int n0 = chunk * 313;
    int n1 = n0 + 313; if (n1 > NPG) n1 = NPG;
    float s = 0.f, ss = 0.f;
    for (int nn = n0; nn < n1; nn++) {
        float v = __ldcs(&buf[((size_t)(b * NPG + nn)) * 128 + c]);
        s += v; ss += v * v;
    }
    atomicAdd(&g_stats[statbase + b * 128 + c], s);
    atomicAdd(&g_stats[statbase + 512 + b * 128 + c], ss);
}
__global__ void finalize_stats_k() {
    int idx = threadIdx.x;  // 1024
    int side = idx >> 9, j = idx & 511;
    float s  = g_stats[side * 1024 + j];
    float ss = g_stats[side * 1024 + 512 + j];
    float mean = s * (1.f / NPG);
    float var  = ss * (1.f / NPG) - mean * mean;
    float inv  = 1.f / (sqrtf(fmaxf(var, 0.f)) + 1e-5f);
    g_mean[idx] = mean;
    g_inv[idx]  = inv;
}

// ---------------- fused norm + leaky + LSTM cell ----------------
__global__ __launch_bounds__(256) void lstm_k(
    const float* __restrict__ cell,
    const float* __restrict__ gx_gamma, const float* __restrict__ gx_beta,
    const float* __restrict__ gh_gamma, const float* __restrict__ gh_beta,
    float* __restrict__ out)
{
    int gid = blockIdx.x * 256 + threadIdx.x;
    if (gid >= BN * 32) return;
    int n = gid >> 5, u = gid & 31;
    int b = n / NPG;

    float xs[4], hs[4];
    #pragma unroll
    for (int q = 0; q < 4; q++) {
        int c = u + 32 * q;
        size_t ix = (size_t)n * 128 + c;
        {
            float v = g_xsum[ix];
            float xn = (v - g_mean[b * 128 + c]) * g_inv[b * 128 + c];
            xs[q] = leaky(fmaf(gx_gamma[ix], xn, gx_beta[ix]));
        }
        {
            float v = g_hsum[ix];
            float xn = (v - g_mean[512 + b * 128 + c]) * g_inv[512 + b * 128 + c];
            hs[q] = leaky(fmaf(gh_gamma[ix], xn, gh_beta[ix]));
        }
    }
    // split order: f, o, i, g
    float fg = sigm(xs[0] + hs[0]);
    float og = sigm(xs[1] + hs[1]);
    float ig = sigm(xs[2] + hs[2]);
    float gg = tanhf(xs[3] + hs[3]);
    float cc = fmaf(fg, cell[gid], ig * gg);
    float nh = og * tanhf(cc);
    out[gid] = cc;
    out[(size_t)BN * 32 + gid] = nh;
}

// ---------------- launcher ----------------
extern "C" void kernel_launch(void* const* d_in, const int* in_sizes, int n_in,
                              void* d_out, int out_size)
{
    const float* x    = (const float*)d_in[0];
    const float* h    = (const float*)d_in[1];
    const float* cell = (const float*)d_in[2];
    const int*   ei   = (const int*)d_in[3];
    const float* gx1_wq = (const float*)d_in[4];  const float* gx1_bq = (const float*)d_in[5];
    const float* gx1_wk = (const float*)d_in[6];  const float* gx1_bk = (const float*)d_in[7];
    const float* gx1_wv = (const float*)d_in[8];  const float* gx1_bv = (const float*)d_in[9];
    const float* gx2_wq = (const float*)d_in[10]; const float* gx2_bq = (const float*)d_in[11];
    const float* gx2_wk = (const float*)d_in[12]; const float* gx2_bk = (const float*)d_in[13];
    const float* gx2_wv = (const float*)d_in[14]; const float* gx2_bv = (const float*)d_in[15];
    const float* gh1_wq = (const float*)d_in[16]; const float* gh1_bq = (const float*)d_in[17];
    const float* gh1_wk = (const float*)d_in[18]; const float* gh1_bk = (const float*)d_in[19];
    const float* gh1_wv = (const float*)d_in[20]; const float* gh1_bv = (const float*)d_in[21];
    const float* gh2_wq = (const float*)d_in[22]; const float* gh2_bq = (const float*)d_in[23];
    const float* gh2_wk = (const float*)d_in[24]; const float* gh2_bk = (const float*)d_in[25];
    const float* gh2_wv = (const float*)d_in[26]; const float* gh2_bv = (const float*)d_in[27];
    const float* gnx_gamma = (const float*)d_in[28];
    const float* gnx_beta  = (const float*)d_in[29];
    const float* gnh_gamma = (const float*)d_in[30];
    const float* gnh_beta  = (const float*)d_in[31];

    int E = in_sizes[3] / 2;

    // CSR build (target-sorted adjacency)
    zero_k<<<(BN + 255) / 256, 256>>>();
    hist_k<<<(E + 255) / 256, 256>>>(ei, E);
    scan_k<<<1, 1024>>>(E);
    scat_k<<<(E + 255) / 256, 256>>>(ei, E);

    // x branch
    gemm_qkv<FDIM><<<dim3(BN / 64, 6), 256>>>(x,
        gx1_wq, gx1_wk, gx1_wv, gx2_wq, gx2_wk, gx2_wv,
        gx1_bq, gx1_bk, gx2_bq, gx2_bk);
    gat_agg<<<BN / 8, 256>>>(gx1_bv, gx2_bv, 0);
    stats_k<<<dim3(32, NB), 128>>>(0);

    // h branch (reuses g_qkv)
    gemm_qkv<UNITS><<<dim3(BN / 64, 6), 256>>>(h,
        gh1_wq, gh1_wk, gh1_wv, gh2_wq, gh2_wk, gh2_wv,
        gh1_bq, gh1_bk, gh2_bq, gh2_bk);
    gat_agg<<<BN / 8, 256>>>(gh1_bv, gh2_bv, 1);
    stats_k<<<dim3(32, NB), 128>>>(1);

    finalize_stats_k<<<1, 1024>>>();
    lstm_k<<<(BN * 32 + 255) / 256, 256>>>(cell, gnx_gamma, gnx_beta, gnh_gamma, gnh_beta,
                                           (float*)d_out);
}

// round 6
// speedup vs baseline: 1.3141x; 1.3141x over previous
#include <cuda_runtime.h>
#include <math.h>

#define BN      40000
#define NPG     10000
#define NB      4
#define G       128
#define UNITS   32
#define FDIM    64

// ---------------- device scratch (no allocations allowed) ----------------
__device__ float g_qkv[6u * (size_t)BN * G];     // Q1,K1,V1,Q2,K2,V2 (reused x then h)
__device__ float g_xsum[(size_t)BN * G];
__device__ float g_hsum[(size_t)BN * G];
__device__ int   g_cnt[BN];
__device__ int   g_offs[BN + 1];
__device__ int   g_cur[BN];
__device__ int   g_colx[640000];
__device__ float g_stats[2048];                  // x: sum[0:512) ss[512:1024); h: +1024
__device__ float g_mean[1024];                   // x: [0:512), h: [512:1024)
__device__ float g_inv[1024];

// ---------------- helpers ----------------
__device__ __forceinline__ float leaky(float v) { return v >= 0.f ? v : 0.2f * v; }

__device__ __forceinline__ unsigned long long pk(float a, float b) {
    unsigned long long r;
    asm("mov.b64 %0, {%1, %2};" : "=l"(r) : "f"(a), "f"(b));
    return r;
}
__device__ __forceinline__ float2 unpk(unsigned long long v) {
    float2 r;
    asm("mov.b64 {%0, %1}, %2;" : "=f"(r.x), "=f"(r.y) : "l"(v));
    return r;
}
__device__ __forceinline__ void fma2(unsigned long long& d, unsigned long long a, unsigned long long b) {
    asm("fma.rn.f32x2 %0, %1, %2, %0;" : "+l"(d) : "l"(a), "l"(b));
}
__device__ __forceinline__ float dot4(float4 a, float4 b) {
    return fmaf(a.x, b.x, fmaf(a.y, b.y, fmaf(a.z, b.z, a.w * b.w)));
}
__device__ __forceinline__ void online_update(float p, float4 v, float& m, float& s, float4& acc) {
    // warp-uniform branch (p, m identical across lanes)
    if (p <= m) {
        float w = __expf(p - m);
        s += w;
        acc.x = fmaf(w, v.x, acc.x); acc.y = fmaf(w, v.y, acc.y);
        acc.z = fmaf(w, v.z, acc.z); acc.w = fmaf(w, v.w, acc.w);
    } else {
        float sc = __expf(m - p);
        s = fmaf(s, sc, 1.f);
        acc.x = fmaf(acc.x, sc, v.x); acc.y = fmaf(acc.y, sc, v.y);
        acc.z = fmaf(acc.z, sc, v.z); acc.w = fmaf(acc.w, sc, v.w);
        m = p;
    }
}
__device__ __forceinline__ float sigm(float x) { return 1.f / (1.f + __expf(-x)); }

// ---------------- CSR build ----------------
__global__ void zero_k() {
    int i = blockIdx.x * 256 + threadIdx.x;
    if (i < BN)   g_cnt[i] = 0;
    if (i < 2048) g_stats[i] = 0.f;
}
__global__ void hist_k(const int* __restrict__ ei, int E) {
    int e = blockIdx.x * 256 + threadIdx.x;
    if (e < E) atomicAdd(&g_cnt[ei[e]], 1);
}
__global__ void scan_k(int E) {
    __shared__ int sh[1024];
    int t = threadIdx.x;
    int base = t * 40;
    int n = BN - base; n = n < 0 ? 0 : (n > 40 ? 40 : n);
    int s = 0;
    for (int i = 0; i < n; i++) s += g_cnt[base + i];
    sh[t] = s; __syncthreads();
    for (int off = 1; off < 1024; off <<= 1) {
        int v = (t >= off) ? sh[t - off] : 0;
        __syncthreads();
        sh[t] += v;
        __syncthreads();
    }
    int run = sh[t] - s;  // exclusive prefix
    for (int i = 0; i < n; i++) {
        g_offs[base + i] = run; g_cur[base + i] = run;
        run += g_cnt[base + i];
    }
    if (t == 0) g_offs[BN] = E;
}
__global__ void scat_k(const int* __restrict__ ei, int E) {
    int e = blockIdx.x * 256 + threadIdx.x;
    if (e < E) {
        int r = ei[e];
        int pos = atomicAdd(&g_cur[r], 1);
        g_colx[pos] = ei[E + e];
    }
}

// ---------------- GEMM: out[m] = (leaky)(x @ W + b), 6 matrices, f32x2 pipes ----------------
template <int DIN>
__global__ __launch_bounds__(256) void gemm_qkv(
    const float* __restrict__ x,
    const float* __restrict__ w0, const float* __restrict__ w1, const float* __restrict__ w2,
    const float* __restrict__ w3, const float* __restrict__ w4, const float* __restrict__ w5,
    const float* __restrict__ b0, const float* __restrict__ b1,
    const float* __restrict__ b3, const float* __restrict__ b4)
{
    __shared__ __align__(16) float ws[DIN * 128];
    __shared__ __align__(16) float xsT[DIN * 64];
    int tid = threadIdx.x;
    int m = blockIdx.y;
    const float* w = (m == 0) ? w0 : (m == 1) ? w1 : (m == 2) ? w2 : (m == 3) ? w3 : (m == 4) ? w4 : w5;
    const float* bias = (m == 0) ? b0 : (m == 1) ? b1 : (m == 3) ? b3 : (m == 4) ? b4 : (const float*)0;
    bool act = (m % 3) != 2;
    int row0 = blockIdx.x * 64;

    const float4* w4p = (const float4*)w;
    float4* ws4 = (float4*)ws;
    #pragma unroll
    for (int i = tid; i < DIN * 32; i += 256) ws4[i] = w4p[i];

    for (int i4 = tid; i4 < DIN * 16; i4 += 256) {
        int r = (i4 * 4) / DIN, k0 = (i4 * 4) % DIN;
        float4 v = *(const float4*)(x + (size_t)(row0 + r) * DIN + k0);
        float vv[4] = {v.x, v.y, v.z, v.w};
        #pragma unroll
        for (int j = 0; j < 4; j++) {
            int k = k0 + j;
            xsT[k * 64 + ((((r >> 2) ^ (k & 15)) << 2) | (r & 3))] = vv[j];
        }
    }
    __syncthreads();

    int lane = tid & 31, warp = tid >> 5;
    int r0 = warp * 8;
    unsigned long long acc[8][2];
    #pragma unroll
    for (int r = 0; r < 8; r++) { acc[r][0] = 0ull; acc[r][1] = 0ull; }

    #pragma unroll 16
    for (int k = 0; k < DIN; k++) {
        float4 wv = *(const float4*)&ws[k * 128 + lane * 4];
        unsigned long long w01 = pk(wv.x, wv.y), w23 = pk(wv.z, wv.w);
        int sw = k & 15;
        float4 a0 = *(const float4*)&xsT[k * 64 + (((r0 >> 2) ^ sw) << 2)];
        float4 a1 = *(const float4*)&xsT[k * 64 + ((((r0 >> 2) + 1) ^ sw) << 2)];
        float ar[8] = {a0.x, a0.y, a0.z, a0.w, a1.x, a1.y, a1.z, a1.w};
        #pragma unroll
        for (int r = 0; r < 8; r++) {
            unsigned long long aa = pk(ar[r], ar[r]);
            fma2(acc[r][0], aa, w01);
            fma2(acc[r][1], aa, w23);
        }
    }

    float4 bv = make_float4(0.f, 0.f, 0.f, 0.f);
    if (bias) bv = ((const float4*)bias)[lane];
    float* out = g_qkv + (size_t)m * (size_t)BN * G;
    #pragma unroll
    for (int r = 0; r < 8; r++) {
        float2 lo = unpk(acc[r][0]), hi = unpk(acc[r][1]);
        float4 res = make_float4(lo.x + bv.x, lo.y + bv.y, hi.x + bv.z, hi.y + bv.w);
        if (act) { res.x = leaky(res.x); res.y = leaky(res.y); res.z = leaky(res.z); res.w = leaky(res.w); }
        *(float4*)(out + (size_t)(row0 + r0 + r) * 128 + lane * 4) = res;
    }
}

// ---------------- fused dual-GAT aggregation (warp/node, 2 edges in flight) ----------------
__global__ __launch_bounds__(256) void gat_agg(
    const float* __restrict__ bv1, const float* __restrict__ bv2, int which)
{
    int wid = (blockIdx.x * 256 + threadIdx.x) >> 5;
    if (wid >= BN) return;
    int lane = threadIdx.x & 31;
    const float4* B4 = (const float4*)g_qkv;
    const size_t M4 = (size_t)BN * 32;
    size_t selfi = (size_t)wid * 32 + lane;

    float4 q1 = __ldcs(B4 + selfi);           // Q streamed-once (evict-first frees L2 for K/V)
    float4 q2 = __ldcs(B4 + M4 * 3 + selfi);

    // self loop
    float4 k1 = B4[M4 + selfi];
    float4 k2 = B4[M4 * 4 + selfi];
    float p1 = dot4(q1, k1), p2 = dot4(q2, k2);
    #pragma unroll
    for (int off = 16; off; off >>= 1) {
        p1 += __shfl_xor_sync(0xffffffffu, p1, off);
        p2 += __shfl_xor_sync(0xffffffffu, p2, off);
    }
    float m1 = p1, s1 = 1.f, m2 = p2, s2 = 1.f;
    float4 acc1 = B4[M4 * 2 + selfi];
    float4 acc2 = B4[M4 * 5 + selfi];

    int start = g_offs[wid], end = g_offs[wid + 1];
    for (int base = start; base < end; base += 32) {
        int e = base + lane;
        int cv = (e < end) ? __ldcs(&g_colx[e]) : 0;
        int cnt = min(32, end - base);
        int j = 0;
        for (; j + 2 <= cnt; j += 2) {
            // two edges in flight: 4 independent score chains, MLP-4 loads
            int sA = __shfl_sync(0xffffffffu, cv, j);
            int sB = __shfl_sync(0xffffffffu, cv, j + 1);
            size_t iA = (size_t)sA * 32 + lane;
            size_t iB = (size_t)sB * 32 + lane;
            float4 kA1 = B4[M4 + iA];
            float4 kB1 = B4[M4 + iB];
            float4 kA2 = B4[M4 * 4 + iA];
            float4 kB2 = B4[M4 * 4 + iB];
            float pA1 = dot4(q1, kA1), pB1 = dot4(q1, kB1);
            float pA2 = dot4(q2, kA2), pB2 = dot4(q2, kB2);
            #pragma unroll
            for (int off = 16; off; off >>= 1) {
                pA1 += __shfl_xor_sync(0xffffffffu, pA1, off);
                pA2 += __shfl_xor_sync(0xffffffffu, pA2, off);
                pB1 += __shfl_xor_sync(0xffffffffu, pB1, off);
                pB2 += __shfl_xor_sync(0xffffffffu, pB2, off);
            }
            float4 vA1 = B4[M4 * 2 + iA];
            float4 vB1 = B4[M4 * 2 + iB];
            float4 vA2 = B4[M4 * 5 + iA];
            float4 vB2 = B4[M4 * 5 + iB];
            online_update(pA1, vA1, m1, s1, acc1);
            online_update(pA2, vA2, m2, s2, acc2);
            online_update(pB1, vB1, m1, s1, acc1);
            online_update(pB2, vB2, m2, s2, acc2);
        }
        if (j < cnt) {
            int src = __shfl_sync(0xffffffffu, cv, j);
            size_t si = (size_t)src * 32 + lane;
            float4 kk1 = B4[M4 + si];
            float4 kk2 = B4[M4 * 4 + si];
            float pa = dot4(q1, kk1), pb = dot4(q2, kk2);
            #pragma unroll
            for (int off = 16; off; off >>= 1) {
                pa += __shfl_xor_sync(0xffffffffu, pa, off);
                pb += __shfl_xor_sync(0xffffffffu, pb, off);
            }
            float4 v1 = B4[M4 * 2 + si];
            float4 v2 = B4[M4 * 5 + si];
            online_update(pa, v1, m1, s1, acc1);
            online_update(pb, v2, m2, s2, acc2);
        }
    }

    float r1 = 1.f / s1, r2 = 1.f / s2;
    float4 bb1 = ((const float4*)bv1)[lane];
    float4 bb2 = ((const float4*)bv2)[lane];
    float4 o;
    o.x = acc1.x * r1 + bb1.x + acc2.x * r2 + bb2.x;
    o.y = acc1.y * r1 + bb1.y + acc2.y * r2 + bb2.y;
    o.z = acc1.z * r1 + bb1.z + acc2.z * r2 + bb2.z;
    o.w = acc1.w * r1 + bb1.w + acc2.w * r2 + bb2.w;
    float* outsum = which ? g_hsum : g_xsum;
    *(float4*)(outsum + selfi * 4) = o;   // plain store: stats_k re-reads this (keep in L2)
}

// ---------------- graph-norm statistics ----------------
__global__ void stats_k(int which) {
    const float* buf = which ? g_hsum : g_xsum;
    int statbase = which ? 1024 : 0;
    int b = blockIdx.y, chunk = blockIdx.x, c = threadIdx.x;  // 128 threads
    int n0 = chunk * 313;
    int n1 = n0 + 313; if (n1 > NPG) n1 = NPG;
    float s = 0.f, ss = 0.f;
    for (int nn = n0; nn < n1; nn++) {
        float v = buf[((size_t)(b * NPG + nn)) * 128 + c];
        s += v; ss += v * v;
    }
    atomicAdd(&g_stats[statbase + b * 128 + c], s);
    atomicAdd(&g_stats[statbase + 512 + b * 128 + c], ss);
}
__global__ void finalize_stats_k() {
    int idx = threadIdx.x;  // 1024
    int side = idx >> 9, j = idx & 511;
    float s  = g_stats[side * 1024 + j];
    float ss = g_stats[side * 1024 + 512 + j];
    float mean = s * (1.f / NPG);
    float var  = ss * (1.f / NPG) - mean * mean;
    float inv  = 1.f / (sqrtf(fmaxf(var, 0.f)) + 1e-5f);
    g_mean[idx] = mean;
    g_inv[idx]  = inv;
}

// ---------------- fused norm + leaky + LSTM cell ----------------
__global__ __launch_bounds__(256) void lstm_k(
    const float* __restrict__ cell,
    const float* __restrict__ gx_gamma, const float* __restrict__ gx_beta,
    const float* __restrict__ gh_gamma, const float* __restrict__ gh_beta,
    float* __restrict__ out)
{
    int gid = blockIdx.x * 256 + threadIdx.x;
    if (gid >= BN * 32) return;
    int n = gid >> 5, u = gid & 31;
    int b = n / NPG;

    float xs[4], hs[4];
    #pragma unroll
    for (int q = 0; q < 4; q++) {
        int c = u + 32 * q;
        size_t ix = (size_t)n * 128 + c;
        {
            float v = g_xsum[ix];
            float xn = (v - g_mean[b * 128 + c]) * g_inv[b * 128 + c];
            xs[q] = leaky(fmaf(gx_gamma[ix], xn, gx_beta[ix]));
        }
        {
            float v = g_hsum[ix];
            float xn = (v - g_mean[512 + b * 128 + c]) * g_inv[512 + b * 128 + c];
            hs[q] = leaky(fmaf(gh_gamma[ix], xn, gh_beta[ix]));
        }
    }
    // split order: f, o, i, g
    float fg = sigm(xs[0] + hs[0]);
    float og = sigm(xs[1] + hs[1]);
    float ig = sigm(xs[2] + hs[2]);
    float gg = tanhf(xs[3] + hs[3]);
    float cc = fmaf(fg, cell[gid], ig * gg);
    float nh = og * tanhf(cc);
    out[gid] = cc;
    out[(size_t)BN * 32 + gid] = nh;
}

// ---------------- launcher ----------------
extern "C" void kernel_launch(void* const* d_in, const int* in_sizes, int n_in,
                              void* d_out, int out_size)
{
    const float* x    = (const float*)d_in[0];
    const float* h    = (const float*)d_in[1];
    const float* cell = (const float*)d_in[2];
    const int*   ei   = (const int*)d_in[3];
    const float* gx1_wq = (const float*)d_in[4];  const float* gx1_bq = (const float*)d_in[5];
    const float* gx1_wk = (const float*)d_in[6];  const float* gx1_bk = (const float*)d_in[7];
    const float* gx1_wv = (const float*)d_in[8];  const float* gx1_bv = (const float*)d_in[9];
    const float* gx2_wq = (const float*)d_in[10]; const float* gx2_bq = (const float*)d_in[11];
    const float* gx2_wk = (const float*)d_in[12]; const float* gx2_bk = (const float*)d_in[13];
    const float* gx2_wv = (const float*)d_in[14]; const float* gx2_bv = (const float*)d_in[15];
    const float* gh1_wq = (const float*)d_in[16]; const float* gh1_bq = (const float*)d_in[17];
    const float* gh1_wk = (const float*)d_in[18]; const float* gh1_bk = (const float*)d_in[19];
    const float* gh1_wv = (const float*)d_in[20]; const float* gh1_bv = (const float*)d_in[21];
    const float* gh2_wq = (const float*)d_in[22]; const float* gh2_bq = (const float*)d_in[23];
    const float* gh2_wk = (const float*)d_in[24]; const float* gh2_bk = (const float*)d_in[25];
    const float* gh2_wv = (const float*)d_in[26]; const float* gh2_bv = (const float*)d_in[27];
    const float* gnx_gamma = (const float*)d_in[28];
    const float* gnx_beta  = (const float*)d_in[29];
    const float* gnh_gamma = (const float*)d_in[30];
    const float* gnh_beta  = (const float*)d_in[31];

    int E = in_sizes[3] / 2;

    // CSR build (target-sorted adjacency)
    zero_k<<<(BN + 255) / 256, 256>>>();
    hist_k<<<(E + 255) / 256, 256>>>(ei, E);
    scan_k<<<1, 1024>>>(E);
    scat_k<<<(E + 255) / 256, 256>>>(ei, E);

    // x branch
    gemm_qkv<FDIM><<<dim3(BN / 64, 6), 256>>>(x,
        gx1_wq, gx1_wk, gx1_wv, gx2_wq, gx2_wk, gx2_wv,
        gx1_bq, gx1_bk, gx2_bq, gx2_bk);
    gat_agg<<<BN / 8, 256>>>(gx1_bv, gx2_bv, 0);
    stats_k<<<dim3(32, NB), 128>>>(0);

    // h branch (reuses g_qkv)
    gemm_qkv<UNITS><<<dim3(BN / 64, 6), 256>>>(h,
        gh1_wq, gh1_wk, gh1_wv, gh2_wq, gh2_wk, gh2_wv,
        gh1_bq, gh1_bk, gh2_bq, gh2_bk);
    gat_agg<<<BN / 8, 256>>>(gh1_bv, gh2_bv, 1);
    stats_k<<<dim3(32, NB), 128>>>(1);

    finalize_stats_k<<<1, 1024>>>();
    lstm_k<<<(BN * 32 + 255) / 256, 256>>>(cell, gnx_gamma, gnx_beta, gnh_gamma, gnh_beta,
                                           (float*)d_out);
}

// round 7
// speedup vs baseline: 1.4821x; 1.1279x over previous
#include <cuda_runtime.h>
#include <math.h>

#define BN      40000
#define NPG     10000
#define NB      4
#define G       128
#define UNITS   32
#define FDIM    64

// ---------------- device scratch (no allocations allowed) ----------------
__device__ float g_qkv[6u * (size_t)BN * G];     // Q1,K1,V1,Q2,K2,V2 (reused x then h)
__device__ float g_xsum[(size_t)BN * G];
__device__ float g_hsum[(size_t)BN * G];
__device__ int   g_cnt[BN];
__device__ int   g_offs[BN + 1];
__device__ int   g_cur[BN];
__device__ int   g_colx[640000];
__device__ float g_stats[2048];                  // x: sum[0:512) ss[512:1024); h: +1024

// ---------------- helpers ----------------
__device__ __forceinline__ float leaky(float v) { return v >= 0.f ? v : 0.2f * v; }

__device__ __forceinline__ unsigned long long pk(float a, float b) {
    unsigned long long r;
    asm("mov.b64 %0, {%1, %2};" : "=l"(r) : "f"(a), "f"(b));
    return r;
}
__device__ __forceinline__ float2 unpk(unsigned long long v) {
    float2 r;
    asm("mov.b64 {%0, %1}, %2;" : "=f"(r.x), "=f"(r.y) : "l"(v));
    return r;
}
__device__ __forceinline__ void fma2(unsigned long long& d, unsigned long long a, unsigned long long b) {
    asm("fma.rn.f32x2 %0, %1, %2, %0;" : "+l"(d) : "l"(a), "l"(b));
}
__device__ __forceinline__ float dot4(float4 a, float4 b) {
    return fmaf(a.x, b.x, fmaf(a.y, b.y, fmaf(a.z, b.z, a.w * b.w)));
}
__device__ __forceinline__ void online_update(float p, float4 v, float& m, float& s, float4& acc) {
    // warp-uniform branch (p, m identical across lanes)
    if (p <= m) {
        float w = __expf(p - m);
        s += w;
        acc.x = fmaf(w, v.x, acc.x); acc.y = fmaf(w, v.y, acc.y);
        acc.z = fmaf(w, v.z, acc.z); acc.w = fmaf(w, v.w, acc.w);
    } else {
        float sc = __expf(m - p);
        s = fmaf(s, sc, 1.f);
        acc.x = fmaf(acc.x, sc, v.x); acc.y = fmaf(acc.y, sc, v.y);
        acc.z = fmaf(acc.z, sc, v.z); acc.w = fmaf(acc.w, sc, v.w);
        m = p;
    }
}
__device__ __forceinline__ float sigm(float x) { return 1.f / (1.f + __expf(-x)); }

// ---------------- CSR build ----------------
__global__ void zero_k() {
    int i = blockIdx.x * 256 + threadIdx.x;
    if (i < BN)   g_cnt[i] = 0;
    if (i < 2048) g_stats[i] = 0.f;
}
__global__ void hist_k(const int* __restrict__ ei, int E) {
    int e = blockIdx.x * 256 + threadIdx.x;
    if (e < E) atomicAdd(&g_cnt[ei[e]], 1);
}
__global__ void scan_k(int E) {
    __shared__ int sh[1024];
    int t = threadIdx.x;
    int base = t * 40;
    int n = BN - base; n = n < 0 ? 0 : (n > 40 ? 40 : n);
    int s = 0;
    for (int i = 0; i < n; i++) s += g_cnt[base + i];
    sh[t] = s; __syncthreads();
    for (int off = 1; off < 1024; off <<= 1) {
        int v = (t >= off) ? sh[t - off] : 0;
        __syncthreads();
        sh[t] += v;
        __syncthreads();
    }
    int run = sh[t] - s;  // exclusive prefix
    for (int i = 0; i < n; i++) {
        g_offs[base + i] = run; g_cur[base + i] = run;
        run += g_cnt[base + i];
    }
    if (t == 0) g_offs[BN] = E;
}
__global__ void scat_k(const int* __restrict__ ei, int E) {
    int e = blockIdx.x * 256 + threadIdx.x;
    if (e < E) {
        int r = ei[e];
        int pos = atomicAdd(&g_cur[r], 1);
        g_colx[pos] = ei[E + e];
    }
}

// ---------------- GEMM: out[m] = (leaky)(x @ W + b), 6 matrices, f32x2 pipes ----------------
template <int DIN>
__global__ __launch_bounds__(256) void gemm_qkv(
    const float* __restrict__ x,
    const float* __restrict__ w0, const float* __restrict__ w1, const float* __restrict__ w2,
    const float* __restrict__ w3, const float* __restrict__ w4, const float* __restrict__ w5,
    const float* __restrict__ b0, const float* __restrict__ b1,
    const float* __restrict__ b3, const float* __restrict__ b4)
{
    __shared__ __align__(16) float ws[DIN * 128];
    __shared__ __align__(16) float xsT[DIN * 64];
    int tid = threadIdx.x;
    int m = blockIdx.y;
    const float* w = (m == 0) ? w0 : (m == 1) ? w1 : (m == 2) ? w2 : (m == 3) ? w3 : (m == 4) ? w4 : w5;
    const float* bias = (m == 0) ? b0 : (m == 1) ? b1 : (m == 3) ? b3 : (m == 4) ? b4 : (const float*)0;
    bool act = (m % 3) != 2;
    int row0 = blockIdx.x * 64;

    const float4* w4p = (const float4*)w;
    float4* ws4 = (float4*)ws;
    #pragma unroll
    for (int i = tid; i < DIN * 32; i += 256) ws4[i] = w4p[i];

    for (int i4 = tid; i4 < DIN * 16; i4 += 256) {
        int r = (i4 * 4) / DIN, k0 = (i4 * 4) % DIN;
        float4 v = *(const float4*)(x + (size_t)(row0 + r) * DIN + k0);
        float vv[4] = {v.x, v.y, v.z, v.w};
        #pragma unroll
        for (int j = 0; j < 4; j++) {
            int k = k0 + j;
            xsT[k * 64 + ((((r >> 2) ^ (k & 15)) << 2) | (r & 3))] = vv[j];
        }
    }
    __syncthreads();

    int lane = tid & 31, warp = tid >> 5;
    int r0 = warp * 8;
    unsigned long long acc[8][2];
    #pragma unroll
    for (int r = 0; r < 8; r++) { acc[r][0] = 0ull; acc[r][1] = 0ull; }

    #pragma unroll 16
    for (int k = 0; k < DIN; k++) {
        float4 wv = *(const float4*)&ws[k * 128 + lane * 4];
        unsigned long long w01 = pk(wv.x, wv.y), w23 = pk(wv.z, wv.w);
        int sw = k & 15;
        float4 a0 = *(const float4*)&xsT[k * 64 + (((r0 >> 2) ^ sw) << 2)];
        float4 a1 = *(const float4*)&xsT[k * 64 + ((((r0 >> 2) + 1) ^ sw) << 2)];
        float ar[8] = {a0.x, a0.y, a0.z, a0.w, a1.x, a1.y, a1.z, a1.w};
        #pragma unroll
        for (int r = 0; r < 8; r++) {
            unsigned long long aa = pk(ar[r], ar[r]);
            fma2(acc[r][0], aa, w01);
            fma2(acc[r][1], aa, w23);
        }
    }

    float4 bv = make_float4(0.f, 0.f, 0.f, 0.f);
    if (bias) bv = ((const float4*)bias)[lane];
    float* out = g_qkv + (size_t)m * (size_t)BN * G;
    #pragma unroll
    for (int r = 0; r < 8; r++) {
        float2 lo = unpk(acc[r][0]), hi = unpk(acc[r][1]);
        float4 res = make_float4(lo.x + bv.x, lo.y + bv.y, hi.x + bv.z, hi.y + bv.w);
        if (act) { res.x = leaky(res.x); res.y = leaky(res.y); res.z = leaky(res.z); res.w = leaky(res.w); }
        *(float4*)(out + (size_t)(row0 + r0 + r) * 128 + lane * 4) = res;
    }
}

// ---------------- fused dual-GAT aggregation (warp per node, online softmax) ----------------
// + fused graph-norm statistics: 8 warps of a block = 8 consecutive nodes, all in
//   one batch (NPG % 8 == 0), so block-reduce sum/sumsq and atomicAdd once per col.
__global__ __launch_bounds__(256) void gat_agg(
    const float* __restrict__ bv1, const float* __restrict__ bv2, int which)
{
    __shared__ float sh_s[8][128];
    __shared__ float sh_q[8][128];

    int warp = threadIdx.x >> 5;
    int wid = blockIdx.x * 8 + warp;     // grid is exactly BN/8 blocks
    int lane = threadIdx.x & 31;
    const float4* B4 = (const float4*)g_qkv;
    const size_t M4 = (size_t)BN * 32;
    size_t selfi = (size_t)wid * 32 + lane;

    float4 q1 = B4[selfi];
    float4 q2 = B4[M4 * 3 + selfi];

    // self loop
    float4 k1 = B4[M4 + selfi];
    float4 k2 = B4[M4 * 4 + selfi];
    float p1 = dot4(q1, k1), p2 = dot4(q2, k2);
    #pragma unroll
    for (int off = 16; off; off >>= 1) {
        p1 += __shfl_xor_sync(0xffffffffu, p1, off);
        p2 += __shfl_xor_sync(0xffffffffu, p2, off);
    }
    float m1 = p1, s1 = 1.f, m2 = p2, s2 = 1.f;
    float4 acc1 = B4[M4 * 2 + selfi];
    float4 acc2 = B4[M4 * 5 + selfi];

    int start = g_offs[wid], end = g_offs[wid + 1];
    for (int base = start; base < end; base += 32) {
        int e = base + lane;
        int cv = (e < end) ? g_colx[e] : 0;
        int cnt = min(32, end - base);
        for (int j = 0; j < cnt; j++) {
            int src = __shfl_sync(0xffffffffu, cv, j);
            size_t si = (size_t)src * 32 + lane;
            float4 kk1 = B4[M4 + si];
            float4 kk2 = B4[M4 * 4 + si];
            float pa = dot4(q1, kk1), pb = dot4(q2, kk2);
            #pragma unroll
            for (int off = 16; off; off >>= 1) {
                pa += __shfl_xor_sync(0xffffffffu, pa, off);
                pb += __shfl_xor_sync(0xffffffffu, pb, off);
            }
            float4 v1 = B4[M4 * 2 + si];
            float4 v2 = B4[M4 * 5 + si];
            online_update(pa, v1, m1, s1, acc1);
            online_update(pb, v2, m2, s2, acc2);
        }
    }

    float r1 = 1.f / s1, r2 = 1.f / s2;
    float4 bb1 = ((const float4*)bv1)[lane];
    float4 bb2 = ((const float4*)bv2)[lane];
    float4 o;
    o.x = acc1.x * r1 + bb1.x + acc2.x * r2 + bb2.x;
    o.y = acc1.y * r1 + bb1.y + acc2.y * r2 + bb2.y;
    o.z = acc1.z * r1 + bb1.z + acc2.z * r2 + bb2.z;
    o.w = acc1.w * r1 + bb1.w + acc2.w * r2 + bb2.w;
    float* outsum = which ? g_hsum : g_xsum;
    *(float4*)(outsum + selfi * 4) = o;

    // ---- fused stats ----
    int c0 = lane * 4;
    sh_s[warp][c0 + 0] = o.x; sh_s[warp][c0 + 1] = o.y;
    sh_s[warp][c0 + 2] = o.z; sh_s[warp][c0 + 3] = o.w;
    sh_q[warp][c0 + 0] = o.x * o.x; sh_q[warp][c0 + 1] = o.y * o.y;
    sh_q[warp][c0 + 2] = o.z * o.z; sh_q[warp][c0 + 3] = o.w * o.w;
    __syncthreads();

    int t = threadIdx.x;
    int c = t & 127, half = t >> 7;           // 0: sum, 1: sumsq
    int b = (blockIdx.x * 8) / NPG;           // whole block in one batch
    int statbase = (which ? 1024 : 0) + half * 512 + b * 128 + c;
    float acc = 0.f;
    const float (*src)[128] = half ? sh_q : sh_s;
    #pragma unroll
    for (int w = 0; w < 8; w++) acc += src[w][c];
    atomicAdd(&g_stats[statbase], acc);
}

// ---------------- fused norm + leaky + LSTM cell (stats finalized inline) ----------------
__global__ __launch_bounds__(256) void lstm_k(
    const float* __restrict__ cell,
    const float* __restrict__ gx_gamma, const float* __restrict__ gx_beta,
    const float* __restrict__ gh_gamma, const float* __restrict__ gh_beta,
    float* __restrict__ out)
{
    int gid = blockIdx.x * 256 + threadIdx.x;
    if (gid >= BN * 32) return;
    int n = gid >> 5, u = gid & 31;
    int b = n / NPG;

    const float invN = 1.f / NPG;
    float xs[4], hs[4];
    #pragma unroll
    for (int q = 0; q < 4; q++) {
        int c = u + 32 * q;
        size_t ix = (size_t)n * 128 + c;
        {
            float s  = g_stats[b * 128 + c];
            float ss = g_stats[512 + b * 128 + c];
            float mean = s * invN;
            float var  = ss * invN - mean * mean;
            float inv  = 1.f / (sqrtf(fmaxf(var, 0.f)) + 1e-5f);
            float xn = (g_xsum[ix] - mean) * inv;
            xs[q] = leaky(fmaf(gx_gamma[ix], xn, gx_beta[ix]));
        }
        {
            float s  = g_stats[1024 + b * 128 + c];
            float ss = g_stats[1536 + b * 128 + c];
            float mean = s * invN;
            float var  = ss * invN - mean * mean;
            float inv  = 1.f / (sqrtf(fmaxf(var, 0.f)) + 1e-5f);
            float xn = (g_hsum[ix] - mean) * inv;
            hs[q] = leaky(fmaf(gh_gamma[ix], xn, gh_beta[ix]));
        }
    }
    // split order: f, o, i, g
    float fg = sigm(xs[0] + hs[0]);
    float og = sigm(xs[1] + hs[1]);
    float ig = sigm(xs[2] + hs[2]);
    float gg = tanhf(xs[3] + hs[3]);
    float cc = fmaf(fg, cell[gid], ig * gg);
    float nh = og * tanhf(cc);
    out[gid] = cc;
    out[(size_t)BN * 32 + gid] = nh;
}

// ---------------- launcher ----------------
extern "C" void kernel_launch(void* const* d_in, const int* in_sizes, int n_in,
                              void* d_out, int out_size)
{
    const float* x    = (const float*)d_in[0];
    const float* h    = (const float*)d_in[1];
    const float* cell = (const float*)d_in[2];
    const int*   ei   = (const int*)d_in[3];
    const float* gx1_wq = (const float*)d_in[4];  const float* gx1_bq = (const float*)d_in[5];
    const float* gx1_wk = (const float*)d_in[6];  const float* gx1_bk = (const float*)d_in[7];
    const float* gx1_wv = (const float*)d_in[8];  const float* gx1_bv = (const float*)d_in[9];
    const float* gx2_wq = (const float*)d_in[10]; const float* gx2_bq = (const float*)d_in[11];
    const float* gx2_wk = (const float*)d_in[12]; const float* gx2_bk = (const float*)d_in[13];
    const float* gx2_wv = (const float*)d_in[14]; const float* gx2_bv = (const float*)d_in[15];
    const float* gh1_wq = (const float*)d_in[16]; const float* gh1_bq = (const float*)d_in[17];
    const float* gh1_wk = (const float*)d_in[18]; const float* gh1_bk = (const float*)d_in[19];
    const float* gh1_wv = (const float*)d_in[20]; const float* gh1_bv = (const float*)d_in[21];
    const float* gh2_wq = (const float*)d_in[22]; const float* gh2_bq = (const float*)d_in[23];
    const float* gh2_wk = (const float*)d_in[24]; const float* gh2_bk = (const float*)d_in[25];
    const float* gh2_wv = (const float*)d_in[26]; const float* gh2_bv = (const float*)d_in[27];
    const float* gnx_gamma = (const float*)d_in[28];
    const float* gnx_beta  = (const float*)d_in[29];
    const float* gnh_gamma = (const float*)d_in[30];
    const float* gnh_beta  = (const float*)d_in[31];

    int E = in_sizes[3] / 2;

    // CSR build (target-sorted adjacency)
    zero_k<<<(BN + 255) / 256, 256>>>();
    hist_k<<<(E + 255) / 256, 256>>>(ei, E);
    scan_k<<<1, 1024>>>(E);
    scat_k<<<(E + 255) / 256, 256>>>(ei, E);

    // x branch
    gemm_qkv<FDIM><<<dim3(BN / 64, 6), 256>>>(x,
        gx1_wq, gx1_wk, gx1_wv, gx2_wq, gx2_wk, gx2_wv,
        gx1_bq, gx1_bk, gx2_bq, gx2_bk);
    gat_agg<<<BN / 8, 256>>>(gx1_bv, gx2_bv, 0);

    // h branch (reuses g_qkv)
    gemm_qkv<UNITS><<<dim3(BN / 64, 6), 256>>>(h,
        gh1_wq, gh1_wk, gh1_wv, gh2_wq, gh2_wk, gh2_wv,
        gh1_bq, gh1_bk, gh2_bq, gh2_bk);
    gat_agg<<<BN / 8, 256>>>(gh1_bv, gh2_bv, 1);

    lstm_k<<<(BN * 32 + 255) / 256, 256>>>(cell, gnx_gamma, gnx_beta, gnh_gamma, gnh_beta,
                                           (float*)d_out);
}